// round 1
// baseline (speedup 1.0000x reference)
#include <cuda_runtime.h>
#include <cuda_bf16.h>
#include <math_constants.h>

// Problem constants
#define BB 8
#define DD 1024
#define LL 2048
static const long long NDL = (long long)DD * LL;          // per-batch x plane
static const long long NBDL = (long long)BB * DD * LL;    // full x tensor
#define CAUCHY_E 1.0100501670841680f                      // exp(0.01)

// ---------------------------------------------------------------------------
// Scratch: one big __device__ array (allowed; no cudaMalloc anywhere)
// Layout (floats):
//  t0      : B*D*L   (also reused as z)
//  t1      : B*D*L
//  dsx,dcx,lsx,lcx : B*D*L each
//  Gd      : B*D*D
//  Gl      : B*L*L
//  nsd,ncd : B*D each
//  nsl,ncl : B*L each
//  csum    : B*D
// ---------------------------------------------------------------------------
#define SCR_TOTAL (6LL*BB*DD*LL + (long long)BB*DD*DD + (long long)BB*LL*LL + 3LL*BB*DD + 2LL*BB*LL)
__device__ float g_scr[SCR_TOTAL];

// ---------------------------------------------------------------------------
// Tiled SGEMM: C = op(A) * op(B) (+bias / +residual)
// TA=0: A is M x K row-major. TA=1: A stored K x M (leading dim M).
// TB=0: B is K x N row-major. TB=1: B stored N x K (leading dim K).
// EPI=0 none; EPI=1 C += bias[row]; EPI=2 C = (acc + resid)/2.
// All of M,N multiples of 128; K multiple of 16 (true for every call here).
// ---------------------------------------------------------------------------
template<int TA, int TB, int EPI>
__global__ void __launch_bounds__(256)
sgemm_kernel(const float* __restrict__ Ag, const float* __restrict__ Bg,
             float* __restrict__ Cg,
             const float* __restrict__ bias,
             const float* __restrict__ resid,
             int M, int N, int K,
             long long sA, long long sB, long long sC)
{
    constexpr int BM = 128, BN = 128, BK = 16, TM = 8, TN = 8;
    __shared__ float As[2][BK][BM];
    __shared__ float Bs[2][BK][BN];

    const int bz = blockIdx.z;
    const float* A = Ag + bz * sA;
    const float* B = Bg + bz * sB;
    float*       C = Cg + bz * sC;
    const float* R = (EPI == 2) ? (resid + bz * sC) : nullptr;

    const int tid = threadIdx.x;
    const int tx  = tid & 15;     // 16 col-groups
    const int ty  = tid >> 4;     // 16 row-groups
    const int mBase = blockIdx.y * BM;
    const int nBase = blockIdx.x * BN;

    float acc[TM][TN] = {};
    float4 ra[2], rb[2];

    const int nTiles = K / BK;

    auto fetch = [&](int kt) {
        const int kb = kt * BK;
#pragma unroll
        for (int i = 0; i < 2; ++i) {
            int idx = tid + i * 256;
            if (TA == 0) {
                int r = idx >> 2, k4 = (idx & 3) << 2;
                ra[i] = *reinterpret_cast<const float4*>(A + (long long)(mBase + r) * K + kb + k4);
            } else {
                int kr = idx >> 5, m4 = (idx & 31) << 2;
                ra[i] = *reinterpret_cast<const float4*>(A + (long long)(kb + kr) * M + mBase + m4);
            }
            if (TB == 0) {
                int kr = idx >> 5, n4 = (idx & 31) << 2;
                rb[i] = *reinterpret_cast<const float4*>(B + (long long)(kb + kr) * N + nBase + n4);
            } else {
                int r = idx >> 2, k4 = (idx & 3) << 2;
                rb[i] = *reinterpret_cast<const float4*>(B + (long long)(nBase + r) * K + kb + k4);
            }
        }
    };

    auto stage = [&](int buf) {
#pragma unroll
        for (int i = 0; i < 2; ++i) {
            int idx = tid + i * 256;
            if (TA == 0) {
                int r = idx >> 2, k4 = (idx & 3) << 2;
                As[buf][k4 + 0][r] = ra[i].x;
                As[buf][k4 + 1][r] = ra[i].y;
                As[buf][k4 + 2][r] = ra[i].z;
                As[buf][k4 + 3][r] = ra[i].w;
            } else {
                int kr = idx >> 5, m4 = (idx & 31) << 2;
                *reinterpret_cast<float4*>(&As[buf][kr][m4]) = ra[i];
            }
            if (TB == 0) {
                int kr = idx >> 5, n4 = (idx & 31) << 2;
                *reinterpret_cast<float4*>(&Bs[buf][kr][n4]) = rb[i];
            } else {
                int r = idx >> 2, k4 = (idx & 3) << 2;
                Bs[buf][k4 + 0][r] = rb[i].x;
                Bs[buf][k4 + 1][r] = rb[i].y;
                Bs[buf][k4 + 2][r] = rb[i].z;
                Bs[buf][k4 + 3][r] = rb[i].w;
            }
        }
    };

    fetch(0);
    stage(0);
    __syncthreads();

    for (int t = 0; t < nTiles; ++t) {
        const int buf = t & 1;
        if (t + 1 < nTiles) fetch(t + 1);
#pragma unroll
        for (int kk = 0; kk < BK; ++kk) {
            float a[TM], bv[TN];
            *reinterpret_cast<float4*>(a)      = *reinterpret_cast<const float4*>(&As[buf][kk][ty * TM]);
            *reinterpret_cast<float4*>(a + 4)  = *reinterpret_cast<const float4*>(&As[buf][kk][ty * TM + 4]);
            *reinterpret_cast<float4*>(bv)     = *reinterpret_cast<const float4*>(&Bs[buf][kk][tx * TN]);
            *reinterpret_cast<float4*>(bv + 4) = *reinterpret_cast<const float4*>(&Bs[buf][kk][tx * TN + 4]);
#pragma unroll
            for (int i = 0; i < TM; ++i)
#pragma unroll
                for (int j = 0; j < TN; ++j)
                    acc[i][j] = fmaf(a[i], bv[j], acc[i][j]);
        }
        if (t + 1 < nTiles) stage(buf ^ 1);
        __syncthreads();
    }

#pragma unroll
    for (int i = 0; i < TM; ++i) {
        const int row = mBase + ty * TM + i;
        const float bvv = (EPI == 1) ? __ldg(&bias[row]) : 0.f;
#pragma unroll
        for (int j = 0; j < TN; j += 4) {
            const long long off = (long long)row * N + nBase + tx * TN + j;
            float4 v;
            v.x = acc[i][j + 0] + bvv;
            v.y = acc[i][j + 1] + bvv;
            v.z = acc[i][j + 2] + bvv;
            v.w = acc[i][j + 3] + bvv;
            if (EPI == 2) {
                float4 r4 = *reinterpret_cast<const float4*>(R + off);
                v.x = (v.x + r4.x) * 0.5f;
                v.y = (v.y + r4.y) * 0.5f;
                v.z = (v.z + r4.z) * 0.5f;
                v.w = (v.w + r4.w) * 0.5f;
            }
            *reinterpret_cast<float4*>(C + off) = v;
        }
    }
}

// ---------------------------------------------------------------------------
// Helpers
// ---------------------------------------------------------------------------
__device__ __forceinline__ float block_reduce_sum(float v) {
    __shared__ float sh[32];
#pragma unroll
    for (int o = 16; o; o >>= 1) v += __shfl_xor_sync(0xFFFFFFFFu, v, o);
    const int lane = threadIdx.x & 31, w = threadIdx.x >> 5;
    if (lane == 0) sh[w] = v;
    __syncthreads();
    if (w == 0) {
        v = (lane < (blockDim.x >> 5)) ? sh[lane] : 0.f;
#pragma unroll
        for (int o = 16; o; o >>= 1) v += __shfl_xor_sync(0xFFFFFFFFu, v, o);
        if (lane == 0) sh[0] = v;
    }
    __syncthreads();
    return sh[0];
}

// out[row] = sum_c X[row, c]^2  (rows contiguous, length C); one block per row
__global__ void rownorm2_kernel(const float* __restrict__ X, float* __restrict__ out, int C) {
    const float* p = X + (long long)blockIdx.x * C;
    float s = 0.f;
    for (int i = threadIdx.x; i < C; i += blockDim.x) { float v = p[i]; s = fmaf(v, v, s); }
    s = block_reduce_sum(s);
    if (threadIdx.x == 0) out[blockIdx.x] = s;
}

// out[b, c] = sum_r X[b, r, c]^2  (thread per column; coalesced)
__global__ void colnorm2_kernel(const float* __restrict__ X, float* __restrict__ out, int Rr, int C) {
    const int b = blockIdx.y;
    const int c = blockIdx.x * blockDim.x + threadIdx.x;
    const float* p = X + (long long)b * Rr * C + c;
    float s = 0.f;
    for (int r = 0; r < Rr; ++r) { float v = p[(long long)r * C]; s = fmaf(v, v, s); }
    out[(long long)b * C + c] = s;
}

// out[b, c] = sum_r G[b, r, c]   (column sums for axis-1 softmax)
__global__ void colsum_kernel(const float* __restrict__ G, float* __restrict__ out, int Rr, int C) {
    const int b = blockIdx.y;
    const int c = blockIdx.x * blockDim.x + threadIdx.x;
    const float* p = G + (long long)b * Rr * C + c;
    float s = 0.f;
    for (int r = 0; r < Rr; ++r) s += p[(long long)r * C];
    out[(long long)b * C + c] = s;
}

// G (b, D, D): g -> exp(relu(0.5 - 0.5*cospi(pow(g^2/(ns[i]*nc[j]), e) - [i==j])))
__global__ void cauchy_exp_d_kernel(float* __restrict__ G,
                                    const float* __restrict__ ns,
                                    const float* __restrict__ nc) {
    const long long idx = (long long)blockIdx.x * blockDim.x + threadIdx.x;
    const int b = (int)(idx >> 20);            // / (D*D)
    const int rem = (int)(idx & (DD * DD - 1));
    const int i = rem >> 10, j = rem & (DD - 1);
    float g = G[idx];
    float r = (g * g) / (ns[b * DD + i] * nc[b * DD + j]);
    float v = powf(r, CAUCHY_E);
    if (i == j) v -= 1.f;
    v = 0.5f - 0.5f * cospif(v);
    v = fmaxf(v, 0.f);
    G[idx] = expf(v);
}

// G[b,i,j] /= s[b,j]
__global__ void divcol_kernel(float* __restrict__ G, const float* __restrict__ s) {
    const long long idx = (long long)blockIdx.x * blockDim.x + threadIdx.x;
    const int b = (int)(idx >> 20);
    const int j = (int)(idx & (DD - 1));
    G[idx] = G[idx] / s[b * DD + j];
}

// G (b, L, L): fused cauchy transform + row softmax (axis=2). One block per row.
__global__ void cauchy_row_softmax_kernel(float* __restrict__ G,
                                          const float* __restrict__ ns,
                                          const float* __restrict__ nc) {
    const int b = blockIdx.x >> 11;            // / L
    const int i = blockIdx.x & (LL - 1);
    float* row = G + (long long)blockIdx.x * LL;
    const float nsi = ns[b * LL + i];
    const float* ncb = nc + b * LL;

    float vals[LL / 256];
    float s = 0.f;
#pragma unroll
    for (int t = 0; t < LL / 256; ++t) {
        const int j = threadIdx.x + t * 256;
        float g = row[j];
        float r = (g * g) / (nsi * ncb[j]);
        float v = powf(r, CAUCHY_E);
        if (i == j) v -= 1.f;
        v = 0.5f - 0.5f * cospif(v);
        v = fmaxf(v, 0.f);
        v = expf(v);               // max(v)<=1 so no max-subtraction needed
        vals[t] = v;
        s += v;
    }
    s = block_reduce_sum(s);
    const float inv = 1.f / s;
#pragma unroll
    for (int t = 0; t < LL / 256; ++t)
        row[threadIdx.x + t * 256] = vals[t] * inv;
}

// ---------------------------------------------------------------------------
// Host-side launch helpers
// ---------------------------------------------------------------------------
static void launch_gemm_mlp(const float* W, const float* X, float* Y, const float* bias) {
    // Y[b] = W (D x D) * X[b] (D x L) + bias
    dim3 grid(LL / 128, DD / 128, BB);
    sgemm_kernel<0, 0, 1><<<grid, 256>>>(W, X, Y, bias, nullptr, DD, LL, DD, 0LL, NDL, NDL);
}

extern "C" void kernel_launch(void* const* d_in, const int* in_sizes, int n_in,
                              void* d_out, int out_size) {
    const float* x  = (const float*)d_in[0];
    const float* W1 = (const float*)d_in[1];
    const float* b1 = (const float*)d_in[2];
    const float* W2 = (const float*)d_in[3];
    const float* b2 = (const float*)d_in[4];
    const float* W3 = (const float*)d_in[5];
    const float* b3 = (const float*)d_in[6];
    const float* W4 = (const float*)d_in[7];
    const float* b4 = (const float*)d_in[8];
    float* y = (float*)d_out;

    float* scr = nullptr;
    cudaGetSymbolAddress((void**)&scr, g_scr);

    float* t0  = scr;
    float* t1  = t0 + NBDL;
    float* dsx = t1 + NBDL;
    float* dcx = dsx + NBDL;
    float* lsx = dcx + NBDL;
    float* lcx = lsx + NBDL;
    float* Gd  = lcx + NBDL;                                   // B*D*D
    float* Gl  = Gd + (long long)BB * DD * DD;                 // B*L*L
    float* nsd = Gl + (long long)BB * LL * LL;
    float* ncd = nsd + BB * DD;
    float* nsl = ncd + BB * DD;
    float* ncl = nsl + BB * LL;
    float* cs  = ncl + BB * LL;
    float* z   = t0;   // reuse after MLPs are done

    const long long DxD = (long long)DD * DD;

    // 4 MLP chains: x -> t0 -> t1 -> out
    const float* Ws[4] = {W1, W2, W3, W4};
    const float* bs[4] = {b1, b2, b3, b4};
    float* outs[4] = {dsx, dcx, lsx, lcx};
    for (int m = 0; m < 4; ++m) {
        launch_gemm_mlp(Ws[m] + 0 * DxD, x,  t0, bs[m] + 0 * DD);
        launch_gemm_mlp(Ws[m] + 1 * DxD, t0, t1, bs[m] + 1 * DD);
        launch_gemm_mlp(Ws[m] + 2 * DxD, t1, outs[m], bs[m] + 2 * DD);
    }

    // ---- dscore path: Gd[b,i,j] = sum_l dsx[b,i,l]*dcx[b,j,l] ----
    {
        dim3 grid(DD / 128, DD / 128, BB);
        sgemm_kernel<0, 1, 0><<<grid, 256>>>(dsx, dcx, Gd, nullptr, nullptr,
                                             DD, DD, LL, NDL, NDL, DxD);
    }
    rownorm2_kernel<<<BB * DD, 256>>>(dsx, nsd, LL);
    rownorm2_kernel<<<BB * DD, 256>>>(dcx, ncd, LL);
    {
        const long long tot = (long long)BB * DD * DD;
        cauchy_exp_d_kernel<<<(unsigned)(tot / 256), 256>>>(Gd, nsd, ncd);
        colsum_kernel<<<dim3(DD / 256, BB), 256>>>(Gd, cs, DD, DD);
        divcol_kernel<<<(unsigned)(tot / 256), 256>>>(Gd, cs);
    }

    // ---- lscore path: Gl[b,m,n] = sum_d lsx[b,d,m]*lcx[b,d,n] ----
    {
        dim3 grid(LL / 128, LL / 128, BB);
        sgemm_kernel<1, 0, 0><<<grid, 256>>>(lsx, lcx, Gl, nullptr, nullptr,
                                             LL, LL, DD, NDL, NDL, (long long)LL * LL);
    }
    colnorm2_kernel<<<dim3(LL / 256, BB), 256>>>(lsx, nsl, DD, LL);
    colnorm2_kernel<<<dim3(LL / 256, BB), 256>>>(lcx, ncl, DD, LL);
    cauchy_row_softmax_kernel<<<BB * LL, 256>>>(Gl, nsl, ncl);

    // ---- z = dscore @ x ----
    {
        dim3 grid(LL / 128, DD / 128, BB);
        sgemm_kernel<0, 0, 0><<<grid, 256>>>(Gd, x, z, nullptr, nullptr,
                                             DD, LL, DD, DxD, NDL, NDL);
    }
    // ---- y = (z @ lscore + x) / 2 ----
    {
        dim3 grid(LL / 128, DD / 128, BB);
        sgemm_kernel<0, 0, 2><<<grid, 256>>>(z, Gl, y, nullptr, x,
                                             DD, LL, LL, NDL, (long long)LL * LL, NDL);
    }
}

// round 5
// speedup vs baseline: 5.1083x; 5.1083x over previous
#include <cuda_runtime.h>
#include <cuda_bf16.h>
#include <math_constants.h>
#include <cstdint>

// Problem constants
#define BB 8
#define DD 1024
#define LL 2048
static const long long NDL = (long long)DD * LL;
static const long long NBDL = (long long)BB * DD * LL;
#define CAUCHY_E 1.0100501670841680f   // exp(0.01)

#define SCR_TOTAL (6LL*BB*DD*LL + (long long)BB*DD*DD + (long long)BB*LL*LL + 3LL*BB*DD + 2LL*BB*LL)
__device__ float g_scr[SCR_TOTAL];

// ---------------------------------------------------------------------------
// PTX helpers
// ---------------------------------------------------------------------------
__device__ __forceinline__ void ldm4(uint32_t* r, const void* p) {
    uint32_t a = (uint32_t)__cvta_generic_to_shared(p);
    asm volatile("ldmatrix.sync.aligned.m8n8.x4.shared.b16 {%0,%1,%2,%3}, [%4];"
                 : "=r"(r[0]), "=r"(r[1]), "=r"(r[2]), "=r"(r[3]) : "r"(a));
}
__device__ __forceinline__ void ldm4t(uint32_t* r, const void* p) {
    uint32_t a = (uint32_t)__cvta_generic_to_shared(p);
    asm volatile("ldmatrix.sync.aligned.m8n8.x4.trans.shared.b16 {%0,%1,%2,%3}, [%4];"
                 : "=r"(r[0]), "=r"(r[1]), "=r"(r[2]), "=r"(r[3]) : "r"(a));
}
__device__ __forceinline__ void mma_bf16(float* d, const uint32_t* a, const uint32_t* b) {
    asm volatile(
        "mma.sync.aligned.m16n8k16.row.col.f32.bf16.bf16.f32 "
        "{%0,%1,%2,%3}, {%4,%5,%6,%7}, {%8,%9}, {%0,%1,%2,%3};"
        : "+f"(d[0]), "+f"(d[1]), "+f"(d[2]), "+f"(d[3])
        : "r"(a[0]), "r"(a[1]), "r"(a[2]), "r"(a[3]), "r"(b[0]), "r"(b[1]));
}
__device__ __forceinline__ void st_bf16x4(__nv_bfloat16* p, float4 v) {
    reinterpret_cast<__nv_bfloat162*>(p)[0] = __floats2bfloat162_rn(v.x, v.y);
    reinterpret_cast<__nv_bfloat162*>(p)[1] = __floats2bfloat162_rn(v.z, v.w);
}

// ---------------------------------------------------------------------------
// bf16 tensor-core GEMM: C = op(A)*op(B) (+bias / +(resid))/2
// TA=0: A row-major MxK. TA=1: A stored KxM (ld M).
// TB=0: B row-major KxN. TB=1: B stored NxK (ld K).
// EPI=0 none; 1 +bias[row]; 2 (acc+resid)/2.
// M,N multiples of 128; K multiple of 32.
// Block 128x128x32, 8 warps each 64x32 via m16n8k16.
// ---------------------------------------------------------------------------
template<int TA, int TB, int EPI>
__global__ void __launch_bounds__(256)
bgemm_kernel(const float* __restrict__ Ag, const float* __restrict__ Bg,
             float* __restrict__ Cg, const float* __restrict__ bias,
             const float* __restrict__ resid,
             int M, int N, int K,
             long long sA, long long sB, long long sC)
{
    constexpr int BM = 128, BN = 128, BK = 32;
    constexpr int AR = TA ? BK : BM, AC = TA ? (BM + 8) : (BK + 8);
    constexpr int BR = TB ? BN : BK, BC = TB ? (BK + 8) : (BN + 8);
    __shared__ __align__(16) __nv_bfloat16 As[2][AR][AC];
    __shared__ __align__(16) __nv_bfloat16 Bs[2][BR][BC];

    const int bz = blockIdx.z;
    const float* A = Ag + bz * sA;
    const float* B = Bg + bz * sB;
    float*       C = Cg + bz * sC;
    const float* R = (EPI == 2) ? (resid + bz * sC) : nullptr;

    const int tid  = threadIdx.x;
    const int lane = tid & 31;
    const int wid  = tid >> 5;
    const int wR   = wid & 1;    // 2 warp-rows of 64
    const int wC   = wid >> 1;   // 4 warp-cols of 32
    const int mBase = blockIdx.y * BM;
    const int nBase = blockIdx.x * BN;
    const int mW = wR * 64;
    const int nW = wC * 32;

    float acc[4][4][4] = {};
    float4 ra[4], rb[4];
    const int nTiles = K / BK;

    auto fetch = [&](int t) {
        const int kb = t * BK;
#pragma unroll
        for (int i = 0; i < 4; ++i) {
            const int fi = tid + i * 256;
            if (TA == 0) {
                int r = fi >> 3, c = (fi & 7) << 2;
                ra[i] = *reinterpret_cast<const float4*>(A + (long long)(mBase + r) * K + kb + c);
            } else {
                int r = fi >> 5, c = (fi & 31) << 2;
                ra[i] = *reinterpret_cast<const float4*>(A + (long long)(kb + r) * M + mBase + c);
            }
            if (TB == 0) {
                int r = fi >> 5, c = (fi & 31) << 2;
                rb[i] = *reinterpret_cast<const float4*>(B + (long long)(kb + r) * N + nBase + c);
            } else {
                int r = fi >> 3, c = (fi & 7) << 2;
                rb[i] = *reinterpret_cast<const float4*>(B + (long long)(nBase + r) * K + kb + c);
            }
        }
    };

    auto stage = [&](int buf) {
#pragma unroll
        for (int i = 0; i < 4; ++i) {
            const int fi = tid + i * 256;
            if (TA == 0) {
                int r = fi >> 3, c = (fi & 7) << 2;
                st_bf16x4(&As[buf][r][c], ra[i]);
            } else {
                int r = fi >> 5, c = (fi & 31) << 2;
                st_bf16x4(&As[buf][r][c], ra[i]);
            }
            if (TB == 0) {
                int r = fi >> 5, c = (fi & 31) << 2;
                st_bf16x4(&Bs[buf][r][c], rb[i]);
            } else {
                int r = fi >> 3, c = (fi & 7) << 2;
                st_bf16x4(&Bs[buf][r][c], rb[i]);
            }
        }
    };

    auto compute = [&](int buf) {
#pragma unroll
        for (int kk = 0; kk < BK; kk += 16) {
            uint32_t a[4][4], b[4][2];
            // A fragments: 4 m16 tiles
#pragma unroll
            for (int mt = 0; mt < 4; ++mt) {
                if (TA == 0) {
                    ldm4(a[mt], &As[buf][mW + mt * 16 + (lane & 15)][kk + ((lane >> 4) << 3)]);
                } else {
                    ldm4t(a[mt], &As[buf][kk + (lane & 7) + ((lane & 16) >> 1)]
                                         [mW + mt * 16 + (lane & 8)]);
                }
            }
            // B fragments: 4 n8 tiles via 2 x4 loads
#pragma unroll
            for (int p = 0; p < 2; ++p) {
                uint32_t r4[4];
                if (TB == 1) {
                    ldm4(r4, &Bs[buf][nW + p * 16 + (lane & 15)][kk + ((lane >> 4) << 3)]);
                } else {
                    ldm4t(r4, &Bs[buf][kk + (lane & 7) + ((lane & 16) >> 1)]
                                      [nW + p * 16 + (lane & 8)]);
                }
                b[2 * p + 0][0] = r4[0]; b[2 * p + 0][1] = r4[2];
                b[2 * p + 1][0] = r4[1]; b[2 * p + 1][1] = r4[3];
            }
#pragma unroll
            for (int mt = 0; mt < 4; ++mt)
#pragma unroll
                for (int nt = 0; nt < 4; ++nt)
                    mma_bf16(acc[mt][nt], a[mt], b[nt]);
        }
    };

    fetch(0);
    stage(0);
    __syncthreads();
    for (int t = 0; t < nTiles; ++t) {
        const int buf = t & 1;
        if (t + 1 < nTiles) fetch(t + 1);
        compute(buf);
        if (t + 1 < nTiles) stage(buf ^ 1);
        __syncthreads();
    }

    // Epilogue
    const int g = lane >> 2, tq = lane & 3;
#pragma unroll
    for (int mt = 0; mt < 4; ++mt) {
        const int row0 = mBase + mW + mt * 16 + g;
#pragma unroll
        for (int half = 0; half < 2; ++half) {
            const int row = row0 + half * 8;
            const float bvv = (EPI == 1) ? __ldg(&bias[row]) : 0.f;
#pragma unroll
            for (int nt = 0; nt < 4; ++nt) {
                const int col = nBase + nW + nt * 8 + tq * 2;
                const long long off = (long long)row * N + col;
                float2 v;
                v.x = acc[mt][nt][half * 2 + 0] + bvv;
                v.y = acc[mt][nt][half * 2 + 1] + bvv;
                if (EPI == 2) {
                    float2 r2 = *reinterpret_cast<const float2*>(R + off);
                    v.x = (v.x + r2.x) * 0.5f;
                    v.y = (v.y + r2.y) * 0.5f;
                }
                *reinterpret_cast<float2*>(C + off) = v;
            }
        }
    }
}

// ---------------------------------------------------------------------------
// Elementwise / reduction helpers (unchanged from R1)
// ---------------------------------------------------------------------------
__device__ __forceinline__ float block_reduce_sum(float v) {
    __shared__ float sh[32];
#pragma unroll
    for (int o = 16; o; o >>= 1) v += __shfl_xor_sync(0xFFFFFFFFu, v, o);
    const int lane = threadIdx.x & 31, w = threadIdx.x >> 5;
    if (lane == 0) sh[w] = v;
    __syncthreads();
    if (w == 0) {
        v = (lane < (blockDim.x >> 5)) ? sh[lane] : 0.f;
#pragma unroll
        for (int o = 16; o; o >>= 1) v += __shfl_xor_sync(0xFFFFFFFFu, v, o);
        if (lane == 0) sh[0] = v;
    }
    __syncthreads();
    return sh[0];
}

__global__ void rownorm2_kernel(const float* __restrict__ X, float* __restrict__ out, int C) {
    const float* p = X + (long long)blockIdx.x * C;
    float s = 0.f;
    for (int i = threadIdx.x; i < C; i += blockDim.x) { float v = p[i]; s = fmaf(v, v, s); }
    s = block_reduce_sum(s);
    if (threadIdx.x == 0) out[blockIdx.x] = s;
}

__global__ void colnorm2_kernel(const float* __restrict__ X, float* __restrict__ out, int Rr, int C) {
    const int b = blockIdx.y;
    const int c = blockIdx.x * blockDim.x + threadIdx.x;
    const float* p = X + (long long)b * Rr * C + c;
    float s = 0.f;
    for (int r = 0; r < Rr; ++r) { float v = p[(long long)r * C]; s = fmaf(v, v, s); }
    out[(long long)b * C + c] = s;
}

__global__ void colsum_kernel(const float* __restrict__ G, float* __restrict__ out, int Rr, int C) {
    const int b = blockIdx.y;
    const int c = blockIdx.x * blockDim.x + threadIdx.x;
    const float* p = G + (long long)b * Rr * C + c;
    float s = 0.f;
    for (int r = 0; r < Rr; ++r) s += p[(long long)r * C];
    out[(long long)b * C + c] = s;
}

__global__ void cauchy_exp_d_kernel(float* __restrict__ G,
                                    const float* __restrict__ ns,
                                    const float* __restrict__ nc) {
    const long long idx = (long long)blockIdx.x * blockDim.x + threadIdx.x;
    const int b = (int)(idx >> 20);
    const int rem = (int)(idx & (DD * DD - 1));
    const int i = rem >> 10, j = rem & (DD - 1);
    float g = G[idx];
    float r = (g * g) / (ns[b * DD + i] * nc[b * DD + j]);
    float v = powf(r, CAUCHY_E);
    if (i == j) v -= 1.f;
    v = 0.5f - 0.5f * cospif(v);
    v = fmaxf(v, 0.f);
    G[idx] = expf(v);
}

__global__ void divcol_kernel(float* __restrict__ G, const float* __restrict__ s) {
    const long long idx = (long long)blockIdx.x * blockDim.x + threadIdx.x;
    const int b = (int)(idx >> 20);
    const int j = (int)(idx & (DD - 1));
    G[idx] = G[idx] / s[b * DD + j];
}

__global__ void cauchy_row_softmax_kernel(float* __restrict__ G,
                                          const float* __restrict__ ns,
                                          const float* __restrict__ nc) {
    const int b = blockIdx.x >> 11;
    const int i = blockIdx.x & (LL - 1);
    float* row = G + (long long)blockIdx.x * LL;
    const float nsi = ns[b * LL + i];
    const float* ncb = nc + b * LL;

    float vals[LL / 256];
    float s = 0.f;
#pragma unroll
    for (int t = 0; t < LL / 256; ++t) {
        const int j = threadIdx.x + t * 256;
        float g = row[j];
        float r = (g * g) / (nsi * ncb[j]);
        float v = powf(r, CAUCHY_E);
        if (i == j) v -= 1.f;
        v = 0.5f - 0.5f * cospif(v);
        v = fmaxf(v, 0.f);
        v = expf(v);
        vals[t] = v;
        s += v;
    }
    s = block_reduce_sum(s);
    const float inv = 1.f / s;
#pragma unroll
    for (int t = 0; t < LL / 256; ++t)
        row[threadIdx.x + t * 256] = vals[t] * inv;
}

// ---------------------------------------------------------------------------
static void launch_gemm_mlp(const float* W, const float* X, float* Y, const float* bias) {
    dim3 grid(LL / 128, DD / 128, BB);
    bgemm_kernel<0, 0, 1><<<grid, 256>>>(W, X, Y, bias, nullptr, DD, LL, DD, 0LL, NDL, NDL);
}

extern "C" void kernel_launch(void* const* d_in, const int* in_sizes, int n_in,
                              void* d_out, int out_size) {
    const float* x  = (const float*)d_in[0];
    const float* W1 = (const float*)d_in[1];
    const float* b1 = (const float*)d_in[2];
    const float* W2 = (const float*)d_in[3];
    const float* b2 = (const float*)d_in[4];
    const float* W3 = (const float*)d_in[5];
    const float* b3 = (const float*)d_in[6];
    const float* W4 = (const float*)d_in[7];
    const float* b4 = (const float*)d_in[8];
    float* y = (float*)d_out;

    float* scr = nullptr;
    cudaGetSymbolAddress((void**)&scr, g_scr);

    float* t0  = scr;
    float* t1  = t0 + NBDL;
    float* dsx = t1 + NBDL;
    float* dcx = dsx + NBDL;
    float* lsx = dcx + NBDL;
    float* lcx = lsx + NBDL;
    float* Gd  = lcx + NBDL;
    float* Gl  = Gd + (long long)BB * DD * DD;
    float* nsd = Gl + (long long)BB * LL * LL;
    float* ncd = nsd + BB * DD;
    float* nsl = ncd + BB * DD;
    float* ncl = nsl + BB * LL;
    float* cs  = ncl + BB * LL;
    float* z   = t0;

    const long long DxD = (long long)DD * DD;

    const float* Ws[4] = {W1, W2, W3, W4};
    const float* bs[4] = {b1, b2, b3, b4};
    float* outs[4] = {dsx, dcx, lsx, lcx};
    for (int m = 0; m < 4; ++m) {
        launch_gemm_mlp(Ws[m] + 0 * DxD, x,  t0, bs[m] + 0 * DD);
        launch_gemm_mlp(Ws[m] + 1 * DxD, t0, t1, bs[m] + 1 * DD);
        launch_gemm_mlp(Ws[m] + 2 * DxD, t1, outs[m], bs[m] + 2 * DD);
    }

    // Gd[b,i,j] = sum_l dsx[b,i,l]*dcx[b,j,l]
    {
        dim3 grid(DD / 128, DD / 128, BB);
        bgemm_kernel<0, 1, 0><<<grid, 256>>>(dsx, dcx, Gd, nullptr, nullptr,
                                             DD, DD, LL, NDL, NDL, DxD);
    }
    rownorm2_kernel<<<BB * DD, 256>>>(dsx, nsd, LL);
    rownorm2_kernel<<<BB * DD, 256>>>(dcx, ncd, LL);
    {
        const long long tot = (long long)BB * DD * DD;
        cauchy_exp_d_kernel<<<(unsigned)(tot / 256), 256>>>(Gd, nsd, ncd);
        colsum_kernel<<<dim3(DD / 256, BB), 256>>>(Gd, cs, DD, DD);
        divcol_kernel<<<(unsigned)(tot / 256), 256>>>(Gd, cs);
    }

    // Gl[b,m,n] = sum_d lsx[b,d,m]*lcx[b,d,n]
    {
        dim3 grid(LL / 128, LL / 128, BB);
        bgemm_kernel<1, 0, 0><<<grid, 256>>>(lsx, lcx, Gl, nullptr, nullptr,
                                             LL, LL, DD, NDL, NDL, (long long)LL * LL);
    }
    colnorm2_kernel<<<dim3(LL / 256, BB), 256>>>(lsx, nsl, DD, LL);
    colnorm2_kernel<<<dim3(LL / 256, BB), 256>>>(lcx, ncl, DD, LL);
    cauchy_row_softmax_kernel<<<BB * LL, 256>>>(Gl, nsl, ncl);

    // z = dscore @ x
    {
        dim3 grid(LL / 128, DD / 128, BB);
        bgemm_kernel<0, 0, 0><<<grid, 256>>>(Gd, x, z, nullptr, nullptr,
                                             DD, LL, DD, DxD, NDL, NDL);
    }
    // y = (z @ lscore + x) / 2
    {
        dim3 grid(LL / 128, DD / 128, BB);
        bgemm_kernel<0, 0, 2><<<grid, 256>>>(z, Gl, y, nullptr, x,
                                             DD, LL, LL, NDL, (long long)LL * LL, NDL);
    }
}

// round 7
// speedup vs baseline: 5.1122x; 1.0008x over previous
#include <cuda_runtime.h>
#include <cuda_bf16.h>
#include <math_constants.h>
#include <cstdint>

// Problem constants
#define BB 8
#define DD 1024
#define LL 2048
static const long long NDL = (long long)DD * LL;
static const long long NBDL = (long long)BB * DD * LL;
#define CAUCHY_E 1.0100501670841680f   // exp(0.01)

#define SCR_TOTAL (6LL*BB*DD*LL + (long long)BB*DD*DD + (long long)BB*LL*LL + 3LL*BB*DD + 2LL*BB*LL)
__device__ float g_scr[SCR_TOTAL];

// ---------------------------------------------------------------------------
// PTX helpers
// ---------------------------------------------------------------------------
__device__ __forceinline__ void ldm4(uint32_t* r, const void* p) {
    uint32_t a = (uint32_t)__cvta_generic_to_shared(p);
    asm volatile("ldmatrix.sync.aligned.m8n8.x4.shared.b16 {%0,%1,%2,%3}, [%4];"
                 : "=r"(r[0]), "=r"(r[1]), "=r"(r[2]), "=r"(r[3]) : "r"(a));
}
__device__ __forceinline__ void ldm4t(uint32_t* r, const void* p) {
    uint32_t a = (uint32_t)__cvta_generic_to_shared(p);
    asm volatile("ldmatrix.sync.aligned.m8n8.x4.trans.shared.b16 {%0,%1,%2,%3}, [%4];"
                 : "=r"(r[0]), "=r"(r[1]), "=r"(r[2]), "=r"(r[3]) : "r"(a));
}
__device__ __forceinline__ void mma_bf16(float* d, const uint32_t* a, const uint32_t* b) {
    asm volatile(
        "mma.sync.aligned.m16n8k16.row.col.f32.bf16.bf16.f32 "
        "{%0,%1,%2,%3}, {%4,%5,%6,%7}, {%8,%9}, {%0,%1,%2,%3};"
        : "+f"(d[0]), "+f"(d[1]), "+f"(d[2]), "+f"(d[3])
        : "r"(a[0]), "r"(a[1]), "r"(a[2]), "r"(a[3]), "r"(b[0]), "r"(b[1]));
}
__device__ __forceinline__ void st_bf16x4(__nv_bfloat16* p, float4 v) {
    reinterpret_cast<__nv_bfloat162*>(p)[0] = __floats2bfloat162_rn(v.x, v.y);
    reinterpret_cast<__nv_bfloat162*>(p)[1] = __floats2bfloat162_rn(v.z, v.w);
}

// ---------------------------------------------------------------------------
// bf16 tensor-core GEMM: C = op(A)*op(B) (+bias / +(resid))/2
// TA=0: A row-major MxK. TA=1: A stored KxM (ld M).
// TB=0: B row-major KxN. TB=1: B stored NxK (ld K).
// EPI=0 none; 1 +bias[row]; 2 (acc+resid)/2.
// M,N multiples of 128; K multiple of 32.
// Block 128x128x32, 8 warps each 64x32 via m16n8k16.
// ---------------------------------------------------------------------------
template<int TA, int TB, int EPI>
__global__ void __launch_bounds__(256)
bgemm_kernel(const float* __restrict__ Ag, const float* __restrict__ Bg,
             float* __restrict__ Cg, const float* __restrict__ bias,
             const float* __restrict__ resid,
             int M, int N, int K,
             long long sA, long long sB, long long sC)
{
    constexpr int BM = 128, BN = 128, BK = 32;
    constexpr int AR = TA ? BK : BM, AC = TA ? (BM + 8) : (BK + 8);
    constexpr int BR = TB ? BN : BK, BC = TB ? (BK + 8) : (BN + 8);
    __shared__ __align__(16) __nv_bfloat16 As[2][AR][AC];
    __shared__ __align__(16) __nv_bfloat16 Bs[2][BR][BC];

    const int bz = blockIdx.z;
    const float* A = Ag + bz * sA;
    const float* B = Bg + bz * sB;
    float*       C = Cg + bz * sC;
    const float* R = (EPI == 2) ? (resid + bz * sC) : nullptr;

    const int tid  = threadIdx.x;
    const int lane = tid & 31;
    const int wid  = tid >> 5;
    const int wR   = wid & 1;    // 2 warp-rows of 64
    const int wC   = wid >> 1;   // 4 warp-cols of 32
    const int mBase = blockIdx.y * BM;
    const int nBase = blockIdx.x * BN;
    const int mW = wR * 64;
    const int nW = wC * 32;

    float acc[4][4][4] = {};
    float4 ra[4], rb[4];
    const int nTiles = K / BK;

    auto fetch = [&](int t) {
        const int kb = t * BK;
#pragma unroll
        for (int i = 0; i < 4; ++i) {
            const int fi = tid + i * 256;
            if (TA == 0) {
                int r = fi >> 3, c = (fi & 7) << 2;
                ra[i] = *reinterpret_cast<const float4*>(A + (long long)(mBase + r) * K + kb + c);
            } else {
                int r = fi >> 5, c = (fi & 31) << 2;
                ra[i] = *reinterpret_cast<const float4*>(A + (long long)(kb + r) * M + mBase + c);
            }
            if (TB == 0) {
                int r = fi >> 5, c = (fi & 31) << 2;
                rb[i] = *reinterpret_cast<const float4*>(B + (long long)(kb + r) * N + nBase + c);
            } else {
                int r = fi >> 3, c = (fi & 7) << 2;
                rb[i] = *reinterpret_cast<const float4*>(B + (long long)(nBase + r) * K + kb + c);
            }
        }
    };

    auto stage = [&](int buf) {
#pragma unroll
        for (int i = 0; i < 4; ++i) {
            const int fi = tid + i * 256;
            if (TA == 0) {
                int r = fi >> 3, c = (fi & 7) << 2;
                st_bf16x4(&As[buf][r][c], ra[i]);
            } else {
                int r = fi >> 5, c = (fi & 31) << 2;
                st_bf16x4(&As[buf][r][c], ra[i]);
            }
            if (TB == 0) {
                int r = fi >> 5, c = (fi & 31) << 2;
                st_bf16x4(&Bs[buf][r][c], rb[i]);
            } else {
                int r = fi >> 3, c = (fi & 7) << 2;
                st_bf16x4(&Bs[buf][r][c], rb[i]);
            }
        }
    };

    auto compute = [&](int buf) {
#pragma unroll
        for (int kk = 0; kk < BK; kk += 16) {
            uint32_t a[4][4], b[4][2];
            // A fragments: 4 m16 tiles
#pragma unroll
            for (int mt = 0; mt < 4; ++mt) {
                if (TA == 0) {
                    ldm4(a[mt], &As[buf][mW + mt * 16 + (lane & 15)][kk + ((lane >> 4) << 3)]);
                } else {
                    ldm4t(a[mt], &As[buf][kk + (lane & 7) + ((lane & 16) >> 1)]
                                         [mW + mt * 16 + (lane & 8)]);
                }
            }
            // B fragments: 4 n8 tiles via 2 x4 loads
#pragma unroll
            for (int p = 0; p < 2; ++p) {
                uint32_t r4[4];
                if (TB == 1) {
                    ldm4(r4, &Bs[buf][nW + p * 16 + (lane & 15)][kk + ((lane >> 4) << 3)]);
                } else {
                    ldm4t(r4, &Bs[buf][kk + (lane & 7) + ((lane & 16) >> 1)]
                                      [nW + p * 16 + (lane & 8)]);
                }
                b[2 * p + 0][0] = r4[0]; b[2 * p + 0][1] = r4[2];
                b[2 * p + 1][0] = r4[1]; b[2 * p + 1][1] = r4[3];
            }
#pragma unroll
            for (int mt = 0; mt < 4; ++mt)
#pragma unroll
                for (int nt = 0; nt < 4; ++nt)
                    mma_bf16(acc[mt][nt], a[mt], b[nt]);
        }
    };

    fetch(0);
    stage(0);
    __syncthreads();
    for (int t = 0; t < nTiles; ++t) {
        const int buf = t & 1;
        if (t + 1 < nTiles) fetch(t + 1);
        compute(buf);
        if (t + 1 < nTiles) stage(buf ^ 1);
        __syncthreads();
    }

    // Epilogue
    const int g = lane >> 2, tq = lane & 3;
#pragma unroll
    for (int mt = 0; mt < 4; ++mt) {
        const int row0 = mBase + mW + mt * 16 + g;
#pragma unroll
        for (int half = 0; half < 2; ++half) {
            const int row = row0 + half * 8;
            const float bvv = (EPI == 1) ? __ldg(&bias[row]) : 0.f;
#pragma unroll
            for (int nt = 0; nt < 4; ++nt) {
                const int col = nBase + nW + nt * 8 + tq * 2;
                const long long off = (long long)row * N + col;
                float2 v;
                v.x = acc[mt][nt][half * 2 + 0] + bvv;
                v.y = acc[mt][nt][half * 2 + 1] + bvv;
                if (EPI == 2) {
                    float2 r2 = *reinterpret_cast<const float2*>(R + off);
                    v.x = (v.x + r2.x) * 0.5f;
                    v.y = (v.y + r2.y) * 0.5f;
                }
                *reinterpret_cast<float2*>(C + off) = v;
            }
        }
    }
}

// ---------------------------------------------------------------------------
// Elementwise / reduction helpers (unchanged from R1)
// ---------------------------------------------------------------------------
__device__ __forceinline__ float block_reduce_sum(float v) {
    __shared__ float sh[32];
#pragma unroll
    for (int o = 16; o; o >>= 1) v += __shfl_xor_sync(0xFFFFFFFFu, v, o);
    const int lane = threadIdx.x & 31, w = threadIdx.x >> 5;
    if (lane == 0) sh[w] = v;
    __syncthreads();
    if (w == 0) {
        v = (lane < (blockDim.x >> 5)) ? sh[lane] : 0.f;
#pragma unroll
        for (int o = 16; o; o >>= 1) v += __shfl_xor_sync(0xFFFFFFFFu, v, o);
        if (lane == 0) sh[0] = v;
    }
    __syncthreads();
    return sh[0];
}

__global__ void rownorm2_kernel(const float* __restrict__ X, float* __restrict__ out, int C) {
    const float* p = X + (long long)blockIdx.x * C;
    float s = 0.f;
    for (int i = threadIdx.x; i < C; i += blockDim.x) { float v = p[i]; s = fmaf(v, v, s); }
    s = block_reduce_sum(s);
    if (threadIdx.x == 0) out[blockIdx.x] = s;
}

__global__ void colnorm2_kernel(const float* __restrict__ X, float* __restrict__ out, int Rr, int C) {
    const int b = blockIdx.y;
    const int c = blockIdx.x * blockDim.x + threadIdx.x;
    const float* p = X + (long long)b * Rr * C + c;
    float s = 0.f;
    for (int r = 0; r < Rr; ++r) { float v = p[(long long)r * C]; s = fmaf(v, v, s); }
    out[(long long)b * C + c] = s;
}

__global__ void colsum_kernel(const float* __restrict__ G, float* __restrict__ out, int Rr, int C) {
    const int b = blockIdx.y;
    const int c = blockIdx.x * blockDim.x + threadIdx.x;
    const float* p = G + (long long)b * Rr * C + c;
    float s = 0.f;
    for (int r = 0; r < Rr; ++r) s += p[(long long)r * C];
    out[(long long)b * C + c] = s;
}

__global__ void cauchy_exp_d_kernel(float* __restrict__ G,
                                    const float* __restrict__ ns,
                                    const float* __restrict__ nc) {
    const long long idx = (long long)blockIdx.x * blockDim.x + threadIdx.x;
    const int b = (int)(idx >> 20);
    const int rem = (int)(idx & (DD * DD - 1));
    const int i = rem >> 10, j = rem & (DD - 1);
    float g = G[idx];
    float r = (g * g) / (ns[b * DD + i] * nc[b * DD + j]);
    float v = powf(r, CAUCHY_E);
    if (i == j) v -= 1.f;
    v = 0.5f - 0.5f * cospif(v);
    v = fmaxf(v, 0.f);
    G[idx] = expf(v);
}

__global__ void divcol_kernel(float* __restrict__ G, const float* __restrict__ s) {
    const long long idx = (long long)blockIdx.x * blockDim.x + threadIdx.x;
    const int b = (int)(idx >> 20);
    const int j = (int)(idx & (DD - 1));
    G[idx] = G[idx] / s[b * DD + j];
}

__global__ void cauchy_row_softmax_kernel(float* __restrict__ G,
                                          const float* __restrict__ ns,
                                          const float* __restrict__ nc) {
    const int b = blockIdx.x >> 11;
    const int i = blockIdx.x & (LL - 1);
    float* row = G + (long long)blockIdx.x * LL;
    const float nsi = ns[b * LL + i];
    const float* ncb = nc + b * LL;

    float vals[LL / 256];
    float s = 0.f;
#pragma unroll
    for (int t = 0; t < LL / 256; ++t) {
        const int j = threadIdx.x + t * 256;
        float g = row[j];
        float r = (g * g) / (nsi * ncb[j]);
        float v = powf(r, CAUCHY_E);
        if (i == j) v -= 1.f;
        v = 0.5f - 0.5f * cospif(v);
        v = fmaxf(v, 0.f);
        v = expf(v);
        vals[t] = v;
        s += v;
    }
    s = block_reduce_sum(s);
    const float inv = 1.f / s;
#pragma unroll
    for (int t = 0; t < LL / 256; ++t)
        row[threadIdx.x + t * 256] = vals[t] * inv;
}

// ---------------------------------------------------------------------------
static void launch_gemm_mlp(const float* W, const float* X, float* Y, const float* bias) {
    dim3 grid(LL / 128, DD / 128, BB);
    bgemm_kernel<0, 0, 1><<<grid, 256>>>(W, X, Y, bias, nullptr, DD, LL, DD, 0LL, NDL, NDL);
}

extern "C" void kernel_launch(void* const* d_in, const int* in_sizes, int n_in,
                              void* d_out, int out_size) {
    const float* x  = (const float*)d_in[0];
    const float* W1 = (const float*)d_in[1];
    const float* b1 = (const float*)d_in[2];
    const float* W2 = (const float*)d_in[3];
    const float* b2 = (const float*)d_in[4];
    const float* W3 = (const float*)d_in[5];
    const float* b3 = (const float*)d_in[6];
    const float* W4 = (const float*)d_in[7];
    const float* b4 = (const float*)d_in[8];
    float* y = (float*)d_out;

    float* scr = nullptr;
    cudaGetSymbolAddress((void**)&scr, g_scr);

    float* t0  = scr;
    float* t1  = t0 + NBDL;
    float* dsx = t1 + NBDL;
    float* dcx = dsx + NBDL;
    float* lsx = dcx + NBDL;
    float* lcx = lsx + NBDL;
    float* Gd  = lcx + NBDL;
    float* Gl  = Gd + (long long)BB * DD * DD;
    float* nsd = Gl + (long long)BB * LL * LL;
    float* ncd = nsd + BB * DD;
    float* nsl = ncd + BB * DD;
    float* ncl = nsl + BB * LL;
    float* cs  = ncl + BB * LL;
    float* z   = t0;

    const long long DxD = (long long)DD * DD;

    const float* Ws[4] = {W1, W2, W3, W4};
    const float* bs[4] = {b1, b2, b3, b4};
    float* outs[4] = {dsx, dcx, lsx, lcx};
    for (int m = 0; m < 4; ++m) {
        launch_gemm_mlp(Ws[m] + 0 * DxD, x,  t0, bs[m] + 0 * DD);
        launch_gemm_mlp(Ws[m] + 1 * DxD, t0, t1, bs[m] + 1 * DD);
        launch_gemm_mlp(Ws[m] + 2 * DxD, t1, outs[m], bs[m] + 2 * DD);
    }

    // Gd[b,i,j] = sum_l dsx[b,i,l]*dcx[b,j,l]
    {
        dim3 grid(DD / 128, DD / 128, BB);
        bgemm_kernel<0, 1, 0><<<grid, 256>>>(dsx, dcx, Gd, nullptr, nullptr,
                                             DD, DD, LL, NDL, NDL, DxD);
    }
    rownorm2_kernel<<<BB * DD, 256>>>(dsx, nsd, LL);
    rownorm2_kernel<<<BB * DD, 256>>>(dcx, ncd, LL);
    {
        const long long tot = (long long)BB * DD * DD;
        cauchy_exp_d_kernel<<<(unsigned)(tot / 256), 256>>>(Gd, nsd, ncd);
        colsum_kernel<<<dim3(DD / 256, BB), 256>>>(Gd, cs, DD, DD);
        divcol_kernel<<<(unsigned)(tot / 256), 256>>>(Gd, cs);
    }

    // Gl[b,m,n] = sum_d lsx[b,d,m]*lcx[b,d,n]
    {
        dim3 grid(LL / 128, LL / 128, BB);
        bgemm_kernel<1, 0, 0><<<grid, 256>>>(lsx, lcx, Gl, nullptr, nullptr,
                                             LL, LL, DD, NDL, NDL, (long long)LL * LL);
    }
    colnorm2_kernel<<<dim3(LL / 256, BB), 256>>>(lsx, nsl, DD, LL);
    colnorm2_kernel<<<dim3(LL / 256, BB), 256>>>(lcx, ncl, DD, LL);
    cauchy_row_softmax_kernel<<<BB * LL, 256>>>(Gl, nsl, ncl);

    // z = dscore @ x
    {
        dim3 grid(LL / 128, DD / 128, BB);
        bgemm_kernel<0, 0, 0><<<grid, 256>>>(Gd, x, z, nullptr, nullptr,
                                             DD, LL, DD, DxD, NDL, NDL);
    }
    // y = (z @ lscore + x) / 2
    {
        dim3 grid(LL / 128, DD / 128, BB);
        bgemm_kernel<0, 0, 2><<<grid, 256>>>(z, Gl, y, nullptr, x,
                                             DD, LL, LL, NDL, (long long)LL * LL, NDL);
    }
}

// round 12
// speedup vs baseline: 6.0683x; 1.1870x over previous
#include <cuda_runtime.h>
#include <cuda_bf16.h>
#include <cstdint>

#define BBATCH 8
#define DDIM 1024
#define LDIM 2048
#define CAUCHY_E 1.0100501670841680f
#define PI_F 3.14159265358979323846f

constexpr long long C_BDL = (long long)BBATCH * DDIM * LDIM;
constexpr long long C_BDD = (long long)BBATCH * DDIM * DDIM;
constexpr long long C_BLL = (long long)BBATCH * LDIM * LDIM;
constexpr long long C_W   = 4LL * 3 * DDIM * DDIM;
constexpr long long EDL   = (long long)DDIM * LDIM;

constexpr long long oGd   = 0;
constexpr long long oGlT  = oGd   + C_BDD * 4;
constexpr long long oXT   = oGlT  + C_BLL * 4;
constexpr long long oT0   = oXT   + C_BDL * 2;
constexpr long long oT1   = oT0   + C_BDL * 2;
constexpr long long oDSXT = oT1   + C_BDL * 2;
constexpr long long oDCXT = oDSXT + C_BDL * 2;
constexpr long long oLSXT = oDCXT + C_BDL * 2;
constexpr long long oLCXT = oLSXT + C_BDL * 2;
constexpr long long oDSX  = oLCXT + C_BDL * 2;
constexpr long long oDCX  = oDSX  + C_BDL * 2;
constexpr long long oWB   = oDCX  + C_BDL * 2;
constexpr long long oGDB  = oWB   + C_W   * 2;
constexpr long long oSLT  = oGDB  + C_BDD * 2;
constexpr long long oZB   = oSLT  + C_BLL * 2;
constexpr long long oNSD  = oZB   + C_BDL * 2;
constexpr long long oNCD  = oNSD  + BBATCH * DDIM * 4;
constexpr long long oNSL  = oNCD  + BBATCH * DDIM * 4;
constexpr long long oNCL  = oNSL  + BBATCH * LDIM * 4;
constexpr long long oCSD  = oNCL  + BBATCH * LDIM * 4;
constexpr long long oCSL  = oCSD  + BBATCH * DDIM * 4;
constexpr long long SCRB  = oCSL  + BBATCH * LDIM * 4;
__device__ __align__(1024) unsigned char g_scr[SCRB];

// ---------------------------------------------------------------------------
__device__ __forceinline__ void ldm4(uint32_t* r, const void* p) {
    uint32_t a = (uint32_t)__cvta_generic_to_shared(p);
    asm volatile("ldmatrix.sync.aligned.m8n8.x4.shared.b16 {%0,%1,%2,%3}, [%4];"
                 : "=r"(r[0]), "=r"(r[1]), "=r"(r[2]), "=r"(r[3]) : "r"(a));
}
__device__ __forceinline__ void mma_bf16(float* d, const uint32_t* a, const uint32_t* b) {
    asm volatile(
        "mma.sync.aligned.m16n8k16.row.col.f32.bf16.bf16.f32 "
        "{%0,%1,%2,%3}, {%4,%5,%6,%7}, {%8,%9}, {%0,%1,%2,%3};"
        : "+f"(d[0]), "+f"(d[1]), "+f"(d[2]), "+f"(d[3])
        : "r"(a[0]), "r"(a[1]), "r"(a[2]), "r"(a[3]), "r"(b[0]), "r"(b[1]));
}
__device__ __forceinline__ void cpa16(void* dst, const void* src) {
    uint32_t d = (uint32_t)__cvta_generic_to_shared(dst);
    asm volatile("cp.async.cg.shared.global [%0], [%1], 16;" :: "r"(d), "l"(src));
}
__device__ __forceinline__ void cpa_commit() { asm volatile("cp.async.commit_group;"); }
template<int N>
__device__ __forceinline__ void cpa_wait() { asm volatile("cp.async.wait_group %0;" :: "n"(N)); }

// ---------------------------------------------------------------------------
// HMMA bf16 GEMM: C[M,N] = A[M,K] * B[N,K]^T, both K-major bf16.
// EPI: 0 fp32 out; 1 +bias[col] bf16 out; 2 (acc+resid)/2 fp32 out; 3 bf16 out.
// Tile 128x128x64, 256 threads (8 warps, 2x4), cp.async double buffer.
// M,N % 128 == 0, K % 64 == 0.
// ---------------------------------------------------------------------------
template<int EPI>
__global__ void __launch_bounds__(256, 2)
hgemm(const __nv_bfloat16* __restrict__ Ag, const __nv_bfloat16* __restrict__ Bg,
      void* __restrict__ Cg, const float* __restrict__ bias,
      const float* __restrict__ resid,
      int M, int N, int K, long long sA, long long sB, long long sC)
{
    constexpr int BK = 64, LDS = 72;             // padded row: 72 bf16 = 144B
    extern __shared__ __nv_bfloat16 smem[];      // As[2][128][72], Bs[2][128][72]
    __nv_bfloat16* Abase = smem;
    __nv_bfloat16* Bbase = smem + 2 * 128 * LDS;

    const int tid = threadIdx.x, lane = tid & 31, wid = tid >> 5;
    const int wR = wid & 1, wC = wid >> 1;
    const int bz = blockIdx.z;
    const __nv_bfloat16* A = Ag + bz * sA;
    const __nv_bfloat16* B = Bg + bz * sB;
    const int mBase = blockIdx.y * 128, nBase = blockIdx.x * 128;
    const int mW = wR * 64, nW = wC * 32;

    // fetch: 128 rows x 64 bf16 = 1024 x 16B chunks per tile; 4 per thread each.
    auto fetch = [&](int t, int buf) {
        const int kb = t * BK;
#pragma unroll
        for (int i = 0; i < 4; ++i) {
            const int fi = tid + i * 256;
            const int r = fi >> 3, c = (fi & 7) << 3;
            cpa16(Abase + (buf * 128 + r) * LDS + c,
                  A + (long long)(mBase + r) * K + kb + c);
        }
#pragma unroll
        for (int i = 0; i < 4; ++i) {
            const int fi = tid + i * 256;
            const int r = fi >> 3, c = (fi & 7) << 3;
            cpa16(Bbase + (buf * 128 + r) * LDS + c,
                  B + (long long)(nBase + r) * K + kb + c);
        }
        cpa_commit();
    };

    float acc[4][4][4] = {};
    const int nT = K / BK;

    fetch(0, 0);
    for (int t = 0; t < nT; ++t) {
        const int buf = t & 1;
        if (t + 1 < nT) { fetch(t + 1, buf ^ 1); cpa_wait<1>(); }
        else            { cpa_wait<0>(); }
        __syncthreads();

        const __nv_bfloat16* As = Abase + buf * 128 * LDS;
        const __nv_bfloat16* Bs = Bbase + buf * 128 * LDS;
#pragma unroll
        for (int kk = 0; kk < BK; kk += 16) {
            uint32_t a[4][4], b[4][2];
#pragma unroll
            for (int mt = 0; mt < 4; ++mt)
                ldm4(a[mt], As + (mW + mt * 16 + (lane & 15)) * LDS + kk + ((lane >> 4) << 3));
#pragma unroll
            for (int p = 0; p < 2; ++p) {
                uint32_t r4[4];
                ldm4(r4, Bs + (nW + p * 16 + (lane & 15)) * LDS + kk + ((lane >> 4) << 3));
                b[2 * p + 0][0] = r4[0]; b[2 * p + 0][1] = r4[2];
                b[2 * p + 1][0] = r4[1]; b[2 * p + 1][1] = r4[3];
            }
#pragma unroll
            for (int mt = 0; mt < 4; ++mt)
#pragma unroll
                for (int nt = 0; nt < 4; ++nt)
                    mma_bf16(acc[mt][nt], a[mt], b[nt]);
        }
        __syncthreads();
    }

    // Epilogue. acc[mt][nt][2*half+j] -> row = mBase+mW+mt*16+g+half*8, col = nBase+nW+nt*8+tq*2+j
    const int g = lane >> 2, tq = lane & 3;
#pragma unroll
    for (int mt = 0; mt < 4; ++mt) {
#pragma unroll
        for (int half = 0; half < 2; ++half) {
            const int row = mBase + mW + mt * 16 + g + half * 8;
#pragma unroll
            for (int nt = 0; nt < 4; ++nt) {
                const int col = nBase + nW + nt * 8 + tq * 2;
                const long long off = (long long)row * N + col;
                float v0 = acc[mt][nt][half * 2 + 0];
                float v1 = acc[mt][nt][half * 2 + 1];
                if (EPI == 1) {
                    v0 += __ldg(&bias[col]);
                    v1 += __ldg(&bias[col + 1]);
                }
                if (EPI == 0) {
                    float* C = (float*)Cg + bz * sC + off;
                    *reinterpret_cast<float2*>(C) = make_float2(v0, v1);
                } else if (EPI == 2) {
                    float* C = (float*)Cg + bz * sC + off;
                    const float* Rp = resid + bz * sC + off;
                    float2 r2 = *reinterpret_cast<const float2*>(Rp);
                    *reinterpret_cast<float2*>(C) = make_float2((v0 + r2.x) * 0.5f,
                                                                (v1 + r2.y) * 0.5f);
                } else {
                    __nv_bfloat16* C = (__nv_bfloat16*)Cg + bz * sC + off;
                    *reinterpret_cast<__nv_bfloat162*>(C) = __floats2bfloat162_rn(v0, v1);
                }
            }
        }
    }
}

// ----------------------------- elementwise --------------------------------
__device__ __forceinline__ float block_reduce_sum(float v) {
    __shared__ float sh[32];
#pragma unroll
    for (int o = 16; o; o >>= 1) v += __shfl_xor_sync(0xFFFFFFFFu, v, o);
    const int lane = threadIdx.x & 31, w = threadIdx.x >> 5;
    if (lane == 0) sh[w] = v;
    __syncthreads();
    if (w == 0) {
        v = (lane < (int)(blockDim.x >> 5)) ? sh[lane] : 0.f;
#pragma unroll
        for (int o = 16; o; o >>= 1) v += __shfl_xor_sync(0xFFFFFFFFu, v, o);
        if (lane == 0) sh[0] = v;
    }
    __syncthreads();
    return sh[0];
}

__global__ void f2b_kernel(const float* __restrict__ in, __nv_bfloat16* __restrict__ out, long long n) {
    for (long long i = (long long)blockIdx.x * blockDim.x + threadIdx.x; i < n;
         i += (long long)gridDim.x * blockDim.x)
        out[i] = __float2bfloat16(in[i]);
}

__global__ void tr_f2b(const float* __restrict__ in, __nv_bfloat16* __restrict__ out, int R, int C) {
    __shared__ float sh[32][33];
    const long long bb = blockIdx.z;
    const float* I = in + bb * (long long)R * C;
    __nv_bfloat16* O = out + bb * (long long)R * C;
    const int c0 = blockIdx.x * 32, r0 = blockIdx.y * 32;
    const int tx = threadIdx.x, ty = threadIdx.y;
#pragma unroll
    for (int i = 0; i < 32; i += 8) sh[ty + i][tx] = I[(long long)(r0 + ty + i) * C + c0 + tx];
    __syncthreads();
#pragma unroll
    for (int i = 0; i < 32; i += 8)
        O[(long long)(c0 + ty + i) * R + r0 + tx] = __float2bfloat16(sh[tx][ty + i]);
}

__global__ void tr_b2b(const __nv_bfloat16* __restrict__ in, __nv_bfloat16* __restrict__ out,
                       int R, int C) {
    __shared__ __nv_bfloat16 sh[32][33];
    const long long bb = blockIdx.z;
    const __nv_bfloat16* I = in + bb * (long long)R * C;
    __nv_bfloat16* O = out + bb * (long long)R * C;
    const int c0 = blockIdx.x * 32, r0 = blockIdx.y * 32;
    const int tx = threadIdx.x, ty = threadIdx.y;
#pragma unroll
    for (int i = 0; i < 32; i += 8) sh[ty + i][tx] = I[(long long)(r0 + ty + i) * C + c0 + tx];
    __syncthreads();
#pragma unroll
    for (int i = 0; i < 32; i += 8) O[(long long)(c0 + ty + i) * R + r0 + tx] = sh[tx][ty + i];
}

__global__ void rownorm_b(const __nv_bfloat16* __restrict__ X, float* __restrict__ out, int C) {
    const __nv_bfloat16* p = X + (long long)blockIdx.x * C;
    float s = 0.f;
    for (int i = threadIdx.x; i < C; i += blockDim.x) {
        float v = __bfloat162float(p[i]);
        s = fmaf(v, v, s);
    }
    s = block_reduce_sum(s);
    if (threadIdx.x == 0) out[blockIdx.x] = s;
}

__global__ void cauchy_exp(float* __restrict__ G, const float* __restrict__ ra,
                           const float* __restrict__ rb, int n) {
    const int b = blockIdx.y, row = blockIdx.x;
    float* g = G + ((long long)b * n + row) * n;
    const float rav = ra[b * n + row];
    const float* rbb = rb + b * n;
    for (int j = threadIdx.x; j < n; j += blockDim.x) {
        float v = g[j];
        float r = (v * v) / (rav * rbb[j]);
        float w = __powf(r, CAUCHY_E);
        if (j == row) w -= 1.f;
        w = 0.5f - 0.5f * __cosf(PI_F * w);
        w = fmaxf(w, 0.f);
        g[j] = __expf(w);
    }
}

__global__ void colsum(const float* __restrict__ G, float* __restrict__ out, int n) {
    const int b = blockIdx.y;
    const int q = blockIdx.x * blockDim.x + threadIdx.x;
    const float* p = G + (long long)b * n * n + q;
    float s = 0.f;
    for (int r = 0; r < n; ++r) s += p[(long long)r * n];
    out[b * n + q] = s;
}

__global__ void divcol_b(const float* __restrict__ G, const float* __restrict__ cs,
                         __nv_bfloat16* __restrict__ out, int n, int sq_shift) {
    const long long tot = (long long)BBATCH * n * n;
    for (long long idx = (long long)blockIdx.x * blockDim.x + threadIdx.x; idx < tot;
         idx += (long long)gridDim.x * blockDim.x) {
        const int q = (int)(idx & (n - 1));
        const int b = (int)(idx >> sq_shift);
        out[idx] = __float2bfloat16(G[idx] / cs[b * n + q]);
    }
}

// ---------------------------------------------------------------------------
extern "C" void kernel_launch(void* const* d_in, const int* in_sizes, int n_in,
                              void* d_out, int out_size) {
    const float* x = (const float*)d_in[0];
    const float* Wf[4] = {(const float*)d_in[1], (const float*)d_in[3],
                          (const float*)d_in[5], (const float*)d_in[7]};
    const float* bf[4] = {(const float*)d_in[2], (const float*)d_in[4],
                          (const float*)d_in[6], (const float*)d_in[8]};
    float* y = (float*)d_out;

    unsigned char* scr = nullptr;
    cudaGetSymbolAddress((void**)&scr, g_scr);

    float* Gd  = (float*)(scr + oGd);
    float* GlT = (float*)(scr + oGlT);
    __nv_bfloat16* xT   = (__nv_bfloat16*)(scr + oXT);
    __nv_bfloat16* t0T  = (__nv_bfloat16*)(scr + oT0);
    __nv_bfloat16* t1T  = (__nv_bfloat16*)(scr + oT1);
    __nv_bfloat16* dsxT = (__nv_bfloat16*)(scr + oDSXT);
    __nv_bfloat16* dcxT = (__nv_bfloat16*)(scr + oDCXT);
    __nv_bfloat16* lsxT = (__nv_bfloat16*)(scr + oLSXT);
    __nv_bfloat16* lcxT = (__nv_bfloat16*)(scr + oLCXT);
    __nv_bfloat16* dsx  = (__nv_bfloat16*)(scr + oDSX);
    __nv_bfloat16* dcx  = (__nv_bfloat16*)(scr + oDCX);
    __nv_bfloat16* Wb   = (__nv_bfloat16*)(scr + oWB);
    __nv_bfloat16* Gdb  = (__nv_bfloat16*)(scr + oGDB);
    __nv_bfloat16* SlTb = (__nv_bfloat16*)(scr + oSLT);
    __nv_bfloat16* zb   = (__nv_bfloat16*)(scr + oZB);
    float* nsd = (float*)(scr + oNSD);
    float* ncd = (float*)(scr + oNCD);
    float* nsl = (float*)(scr + oNSL);
    float* ncl = (float*)(scr + oNCL);
    float* csd = (float*)(scr + oCSD);
    float* csl = (float*)(scr + oCSL);

    const int smemB = 4 * 128 * 72 * 2;   // 73728 B
    cudaFuncSetAttribute(hgemm<0>, cudaFuncAttributeMaxDynamicSharedMemorySize, smemB);
    cudaFuncSetAttribute(hgemm<1>, cudaFuncAttributeMaxDynamicSharedMemorySize, smemB);
    cudaFuncSetAttribute(hgemm<2>, cudaFuncAttributeMaxDynamicSharedMemorySize, smemB);
    cudaFuncSetAttribute(hgemm<3>, cudaFuncAttributeMaxDynamicSharedMemorySize, smemB);

    const long long DxD = (long long)DDIM * DDIM;
    const long long LxL = (long long)LDIM * LDIM;

    for (int m = 0; m < 4; ++m)
        f2b_kernel<<<2048, 256>>>(Wf[m], Wb + (long long)m * 3 * DxD, 3LL * DxD);
    tr_f2b<<<dim3(LDIM / 32, DDIM / 32, BBATCH), dim3(32, 8)>>>(x, xT, DDIM, LDIM);

    // MLPs transposed: YT[l,o] = sum_i prevT[l,i] * W[o,i] + b[o]
    __nv_bfloat16* outsT[4] = {dsxT, dcxT, lsxT, lcxT};
    for (int m = 0; m < 4; ++m) {
        const __nv_bfloat16* W0 = Wb + ((long long)m * 3 + 0) * DxD;
        const __nv_bfloat16* W1 = Wb + ((long long)m * 3 + 1) * DxD;
        const __nv_bfloat16* W2 = Wb + ((long long)m * 3 + 2) * DxD;
        dim3 g(DDIM / 128, LDIM / 128, BBATCH);
        hgemm<1><<<g, 256, smemB>>>(xT,  W0, t0T, bf[m] + 0 * DDIM, nullptr,
                                    LDIM, DDIM, DDIM, EDL, 0LL, EDL);
        hgemm<1><<<g, 256, smemB>>>(t0T, W1, t1T, bf[m] + 1 * DDIM, nullptr,
                                    LDIM, DDIM, DDIM, EDL, 0LL, EDL);
        hgemm<1><<<g, 256, smemB>>>(t1T, W2, outsT[m], bf[m] + 2 * DDIM, nullptr,
                                    LDIM, DDIM, DDIM, EDL, 0LL, EDL);
    }

    tr_b2b<<<dim3(DDIM / 32, LDIM / 32, BBATCH), dim3(32, 8)>>>(dsxT, dsx, LDIM, DDIM);
    tr_b2b<<<dim3(DDIM / 32, LDIM / 32, BBATCH), dim3(32, 8)>>>(dcxT, dcx, LDIM, DDIM);

    // Gd[i,j] = sum_l dsx[i,l] dcx[j,l]
    hgemm<0><<<dim3(DDIM / 128, DDIM / 128, BBATCH), 256, smemB>>>(
        dsx, dcx, Gd, nullptr, nullptr, DDIM, DDIM, LDIM, EDL, EDL, DxD);

    rownorm_b<<<BBATCH * DDIM, 256>>>(dsx, nsd, LDIM);
    rownorm_b<<<BBATCH * DDIM, 256>>>(dcx, ncd, LDIM);
    rownorm_b<<<BBATCH * LDIM, 256>>>(lsxT, nsl, DDIM);
    rownorm_b<<<BBATCH * LDIM, 256>>>(lcxT, ncl, DDIM);

    // dscore: cauchy + softmax over axis 1 (columns of Gd)
    cauchy_exp<<<dim3(DDIM, BBATCH), 256>>>(Gd, nsd, ncd, DDIM);
    colsum<<<dim3(DDIM / 256, BBATCH), 256>>>(Gd, csd, DDIM);
    divcol_b<<<4096, 256>>>(Gd, csd, Gdb, DDIM, 20);

    // GlT[p,q] = Gl[q,p] = sum_d lcxT[p,d] lsxT[q,d]
    hgemm<0><<<dim3(LDIM / 128, LDIM / 128, BBATCH), 256, smemB>>>(
        lcxT, lsxT, GlT, nullptr, nullptr, LDIM, LDIM, DDIM, EDL, EDL, LxL);

    // row-softmax of Gl over axis 2 == column-softmax of GlT; denom ncl[p]*nsl[q]
    cauchy_exp<<<dim3(LDIM, BBATCH), 256>>>(GlT, ncl, nsl, LDIM);
    colsum<<<dim3(LDIM / 256, BBATCH), 256>>>(GlT, csl, LDIM);
    divcol_b<<<8192, 256>>>(GlT, csl, SlTb, LDIM, 22);

    // z[d,l] = sum_e dscore[d,e] x[e,l]   (B = xT, K-major over e)
    hgemm<3><<<dim3(LDIM / 128, DDIM / 128, BBATCH), 256, smemB>>>(
        Gdb, xT, zb, nullptr, nullptr, DDIM, LDIM, DDIM, DxD, EDL, EDL);

    // y[d,l] = (sum_p z[d,p] lscore[p,l] + x[d,l]) / 2   (B = SlTb = lscore^T)
    hgemm<2><<<dim3(LDIM / 128, DDIM / 128, BBATCH), 256, smemB>>>(
        zb, SlTb, y, nullptr, x, DDIM, LDIM, LDIM, EDL, LxL, EDL);
}